// round 14
// baseline (speedup 1.0000x reference)
#include <cuda_runtime.h>
#include <cuda_fp16.h>
#include <cstdint>

#define NN   40000
#define EE   640000
#define FIN  128
#define FHID 256
#define FCLS 40

#define SCAN_BLK 256
#define NSB ((NN + SCAN_BLK - 1) / SCAN_BLK)   // 157

#define FILL_BLKS ((EE / 4 + 255) / 256)         // 625
#define CONV_BLKS ((NN * (FIN / 4) + 255) / 256) // 5000 (float4 per thread)

// ---- scratch (no allocation allowed -> __device__ globals) ----
__device__ int    g_deg[NN];
__device__ int    g_rowptr[NN + 1];
__device__ int    g_cur[NN];
__device__ int    g_colidx[EE];
__device__ int    g_bsum[NSB];
__device__ float  g_norm[NN];
__device__ float  g_norm2[NN];
__device__ __half g_feat_h[NN * FIN];   // norm * X        (fp16)
__device__ __half g_buf1h[NN * FIN];    // N^2 A N X       (fp16)

// ---------------------------------------------------------------
__device__ __forceinline__ void mma_f16(float c[4],
                                        unsigned a0, unsigned a1, unsigned a2, unsigned a3,
                                        unsigned b0, unsigned b1) {
    asm volatile(
        "mma.sync.aligned.m16n8k16.row.col.f32.f16.f16.f32 "
        "{%0,%1,%2,%3}, {%4,%5,%6,%7}, {%8,%9}, {%0,%1,%2,%3};"
        : "+f"(c[0]), "+f"(c[1]), "+f"(c[2]), "+f"(c[3])
        : "r"(a0), "r"(a1), "r"(a2), "r"(a3), "r"(b0), "r"(b1));
}

// ---------------------------------------------------------------
// degree histogram (no-return atomics -> REDG), 4 edges/thread
__global__ void count_deg_kernel(const int* __restrict__ dst) {
    int e = blockIdx.x * blockDim.x + threadIdx.x;
    if (e < EE / 4) {
        int4 d = ((const int4*)dst)[e];
        atomicAdd(&g_deg[d.x], 1);
        atomicAdd(&g_deg[d.y], 1);
        atomicAdd(&g_deg[d.z], 1);
        atomicAdd(&g_deg[d.w], 1);
    }
}

// ---- 2-phase scan: block sums, then per-block base computed in-place ----
__global__ void scan_phase1() {
    __shared__ int wsum[8];
    int tid = threadIdx.x, w = tid >> 5, l = tid & 31;
    int i = blockIdx.x * SCAN_BLK + tid;
    int s = (i < NN) ? g_deg[i] : 0;
#pragma unroll
    for (int o = 16; o; o >>= 1) s += __shfl_down_sync(~0u, s, o);
    if (l == 0) wsum[w] = s;
    __syncthreads();
    if (tid == 0) {
        int t = 0;
#pragma unroll
        for (int k = 0; k < 8; k++) t += wsum[k];
        g_bsum[blockIdx.x] = t;
    }
}

__global__ void scan_phase3() {
    __shared__ int ws[8];
    __shared__ int bsr[8];
    const int bid = blockIdx.x;
    int tid = threadIdx.x, w = tid >> 5, l = tid & 31;

    // block base = sum of g_bsum[0..bid)  (NSB=157 <= 256 threads)
    int bv = (tid < bid) ? g_bsum[tid] : 0;
#pragma unroll
    for (int o = 16; o; o >>= 1) bv += __shfl_down_sync(~0u, bv, o);
    if (l == 0) bsr[w] = bv;

    int i = bid * SCAN_BLK + tid;
    int v = (i < NN) ? g_deg[i] : 0;
    int incl = v;
#pragma unroll
    for (int o = 1; o < 32; o <<= 1) {
        int t = __shfl_up_sync(~0u, incl, o);
        if (l >= o) incl += t;
    }
    if (l == 31) ws[w] = incl;
    __syncthreads();
    if (tid < 8) {
        int t = ws[tid];
#pragma unroll
        for (int o = 1; o < 8; o <<= 1) {
            int u = __shfl_up_sync(0xffu, t, o);
            if (tid >= o) t += u;
        }
        ws[tid] = t;
    }
    __syncthreads();
    int base = bsr[0] + bsr[1] + bsr[2] + bsr[3] +
               bsr[4] + bsr[5] + bsr[6] + bsr[7];
    int excl = base + ((w > 0) ? ws[w - 1] : 0) + incl - v;
    if (i < NN) {
        g_rowptr[i] = excl;
        g_cur[i]    = excl;
        float dn = fmaxf((float)v, 1.0f);
        float nv = rsqrtf(dn);
        g_norm[i]  = nv;
        g_norm2[i] = nv * nv;
        if (i == NN - 1) g_rowptr[NN] = excl + v;
    }
}

// ---------------------------------------------------------------
// FUSED: CSR fill (blocks 0..FILL_BLKS-1) + fp16 feature conversion (rest).
__global__ void fill_conv_kernel(const int* __restrict__ src,
                                 const int* __restrict__ dst,
                                 const float* __restrict__ X) {
    int b = blockIdx.x;
    if (b < FILL_BLKS) {
        int e = b * 256 + threadIdx.x;
        if (e < EE / 4) {
            int4 s = ((const int4*)src)[e];
            int4 d = ((const int4*)dst)[e];
            g_colidx[atomicAdd(&g_cur[d.x], 1)] = s.x;
            g_colidx[atomicAdd(&g_cur[d.y], 1)] = s.y;
            g_colidx[atomicAdd(&g_cur[d.z], 1)] = s.z;
            g_colidx[atomicAdd(&g_cur[d.w], 1)] = s.w;
        }
    } else {
        int i = (b - FILL_BLKS) * 256 + threadIdx.x;   // float4 index
        if (i < NN * (FIN / 4)) {
            int row = i >> 5;
            float4 v = ((const float4*)X)[i];
            float nv = __ldg(&g_norm[row]);
            uint2 o;
            *(__half2*)&o.x = __floats2half2_rn(v.x * nv, v.y * nv);
            *(__half2*)&o.y = __floats2half2_rn(v.z * nv, v.w * nv);
            ((uint2*)g_feat_h)[i] = o;
        }
    }
}

// ---------------------------------------------------------------
// hop1, fp16 rows, MLP=4 (proven loop): warp per dst node.
__global__ void hop_h_kernel(const __half* __restrict__ hin,
                             __half* __restrict__ hout,
                             const float* __restrict__ oscale) {
    int w    = (blockIdx.x * blockDim.x + threadIdx.x) >> 5;
    int lane = threadIdx.x & 31;
    if (w >= NN) return;

    int j  = g_rowptr[w];
    int je = g_rowptr[w + 1];

    const uint2* hin2 = (const uint2*)hin;
    float4 accA = make_float4(0.f, 0.f, 0.f, 0.f);
    float4 accB = make_float4(0.f, 0.f, 0.f, 0.f);

#define ACC(ACCV, V)                                         \
    {                                                        \
        float2 _p0 = __half22float2(*(__half2*)&(V).x);      \
        float2 _p1 = __half22float2(*(__half2*)&(V).y);      \
        ACCV.x += _p0.x; ACCV.y += _p0.y;                    \
        ACCV.z += _p1.x; ACCV.w += _p1.y;                    \
    }

    for (; j + 4 <= je; j += 4) {
        int s0 = __ldg(&g_colidx[j]);
        int s1 = __ldg(&g_colidx[j + 1]);
        int s2 = __ldg(&g_colidx[j + 2]);
        int s3 = __ldg(&g_colidx[j + 3]);
        uint2 v0 = hin2[s0 * 32 + lane];
        uint2 v1 = hin2[s1 * 32 + lane];
        uint2 v2 = hin2[s2 * 32 + lane];
        uint2 v3 = hin2[s3 * 32 + lane];
        ACC(accA, v0) ACC(accB, v1) ACC(accA, v2) ACC(accB, v3)
    }
    if (j + 2 <= je) {
        int s0 = __ldg(&g_colidx[j]);
        int s1 = __ldg(&g_colidx[j + 1]);
        uint2 v0 = hin2[s0 * 32 + lane];
        uint2 v1 = hin2[s1 * 32 + lane];
        ACC(accA, v0) ACC(accB, v1)
        j += 2;
    }
    if (j < je) {
        int s0 = __ldg(&g_colidx[j]);
        uint2 v0 = hin2[s0 * 32 + lane];
        ACC(accA, v0)
    }
#undef ACC

    float os = oscale[w];
    float4 acc;
    acc.x = (accA.x + accB.x) * os;
    acc.y = (accA.y + accB.y) * os;
    acc.z = (accA.z + accB.z) * os;
    acc.w = (accA.w + accB.w) * os;

    uint2 o;
    *(__half2*)&o.x = __floats2half2_rn(acc.x, acc.y);
    *(__half2*)&o.y = __floats2half2_rn(acc.z, acc.w);
    ((uint2*)hout)[w * 32 + lane] = o;
}

// ---------------------------------------------------------------
// FUSED hop2 + MLP head (fp16 tensor cores, fp32 accumulate), 34KB static smem.
// Each block: gather hop2 for its 64 rows from buf1h into a resident fp16
// A-tile, then out = relu(A @ W1 + b1) @ W2 + b2.
#define ASH 136   // Afull stride in halves (68 u32; step 4 mod 32 -> conflict-free)
#define BPS 264   // Bp stride in u32      (step 8 -> conflict-free)
#define HSS 36    // Hs stride in u32      (step 4 -> conflict-free)
#define WSS 40    // Ws stride in u32      (step 8 -> conflict-free)

__global__ __launch_bounds__(256) void gemm12_fused(
    const __half* __restrict__ B1h,    // buf1h
    const float* __restrict__ W1,
    const float* __restrict__ b1,
    const float* __restrict__ W2,
    const float* __restrict__ b2,
    float* __restrict__ out) {
    // Afull: 64*136 halves = 4352 u32 @0; Bp: 16*264 = 4224 u32 @4352  (34304 B)
    // phase2 aliases: Hs 64*36=2304 u32 @0; Ws 32*40=1280 u32 @2304
    __shared__ __align__(16) unsigned SM[4352 + 16 * BPS];
    __half*   As16 = (__half*)SM;
    unsigned* Bp32 = SM + 4352;
    unsigned* Hs32 = SM;
    unsigned* Ws32 = SM + 2304;

    const int tid  = threadIdx.x;
    const int lane = tid & 31;
    const int warp = tid >> 5;
    const int wm   = warp >> 2;        // 0..1
    const int wn   = warp & 3;         // 0..3
    const int row0 = blockIdx.x * 64;
    const int g    = lane >> 2;        // 0..7
    const int tk   = lane & 3;         // 0..3

    // ---------------- phase 0: gather hop2 rows into Afull ----------------
    {
        const uint2* hin2 = (const uint2*)B1h;
#define ACC(ACCV, V)                                         \
        {                                                    \
            float2 _p0 = __half22float2(*(__half2*)&(V).x);  \
            float2 _p1 = __half22float2(*(__half2*)&(V).y);  \
            ACCV.x += _p0.x; ACCV.y += _p0.y;                \
            ACCV.z += _p1.x; ACCV.w += _p1.y;                \
        }
        for (int rr = 0; rr < 8; rr++) {
            int row  = warp * 8 + rr;
            int node = row0 + row;
            int j  = g_rowptr[node];
            int je = g_rowptr[node + 1];
            float4 accA = make_float4(0.f, 0.f, 0.f, 0.f);
            float4 accB = make_float4(0.f, 0.f, 0.f, 0.f);
            for (; j + 4 <= je; j += 4) {
                int s0 = __ldg(&g_colidx[j]);
                int s1 = __ldg(&g_colidx[j + 1]);
                int s2 = __ldg(&g_colidx[j + 2]);
                int s3 = __ldg(&g_colidx[j + 3]);
                uint2 v0 = hin2[s0 * 32 + lane];
                uint2 v1 = hin2[s1 * 32 + lane];
                uint2 v2 = hin2[s2 * 32 + lane];
                uint2 v3 = hin2[s3 * 32 + lane];
                ACC(accA, v0) ACC(accB, v1) ACC(accA, v2) ACC(accB, v3)
            }
            if (j + 2 <= je) {
                int s0 = __ldg(&g_colidx[j]);
                int s1 = __ldg(&g_colidx[j + 1]);
                uint2 v0 = hin2[s0 * 32 + lane];
                uint2 v1 = hin2[s1 * 32 + lane];
                ACC(accA, v0) ACC(accB, v1)
                j += 2;
            }
            if (j < je) {
                int s0 = __ldg(&g_colidx[j]);
                uint2 v0 = hin2[s0 * 32 + lane];
                ACC(accA, v0)
            }
            float os = __ldg(&g_norm[node]);
            uint2 o;
            *(__half2*)&o.x = __floats2half2_rn((accA.x + accB.x) * os,
                                                (accA.y + accB.y) * os);
            *(__half2*)&o.y = __floats2half2_rn((accA.z + accB.z) * os,
                                                (accA.w + accB.w) * os);
            *(uint2*)(As16 + row * ASH + lane * 4) = o;
        }
#undef ACC
    }
    __syncthreads();

    float c[2][8][4];
#pragma unroll
    for (int i = 0; i < 2; i++)
#pragma unroll
        for (int jj = 0; jj < 8; jj++)
#pragma unroll
            for (int q = 0; q < 4; q++) c[i][jj][q] = 0.f;

    // ---------------- phase 1: H = A @ W1 ----------------
    const unsigned* As32 = (const unsigned*)As16;
    for (int kk = 0; kk < 4; kk++) {
        // stage packed W1 chunk: 16 k-pairs x 256 n
#pragma unroll
        for (int l = 0; l < 4; l++) {
            int f    = tid + l * 256;
            int kp   = f >> 6;
            int n4   = (f & 63) * 4;
            int krow = kk * 32 + 2 * kp;
            float4 w0 = *(const float4*)(W1 + krow * FHID + n4);
            float4 w1 = *(const float4*)(W1 + (krow + 1) * FHID + n4);
            uint4 pk;
            { __half2 p = __floats2half2_rn(w0.x, w1.x); pk.x = *(unsigned*)&p; }
            { __half2 p = __floats2half2_rn(w0.y, w1.y); pk.y = *(unsigned*)&p; }
            { __half2 p = __floats2half2_rn(w0.z, w1.z); pk.z = *(unsigned*)&p; }
            { __half2 p = __floats2half2_rn(w0.w, w1.w); pk.w = *(unsigned*)&p; }
            *(uint4*)(Bp32 + kp * BPS + n4) = pk;
        }
        __syncthreads();

#pragma unroll
        for (int s = 0; s < 2; s++) {
            int p = tk + s * 8;
            unsigned a[2][4];
#pragma unroll
            for (int mt = 0; mt < 2; mt++) {
                int rb = wm * 32 + mt * 16 + g;
                a[mt][0] = As32[rb * (ASH / 2) + kk * 16 + p];
                a[mt][1] = As32[(rb + 8) * (ASH / 2) + kk * 16 + p];
                a[mt][2] = As32[rb * (ASH / 2) + kk * 16 + p + 4];
                a[mt][3] = As32[(rb + 8) * (ASH / 2) + kk * 16 + p + 4];
            }
#pragma unroll
            for (int nt = 0; nt < 8; nt++) {
                int n = wn * 64 + nt * 8 + g;
                unsigned b0  = Bp32[p * BPS + n];
                unsigned b1v = Bp32[(p + 4) * BPS + n];
#pragma unroll
                for (int mt = 0; mt < 2; mt++)
                    mma_f16(c[mt][nt], a[mt][0], a[mt][1], a[mt][2], a[mt][3],
                            b0, b1v);
            }
        }
        __syncthreads();
    }

    // ---------------- phase 2: out = relu(H + b1) @ W2 + b2 ----------------
    const int half2nd = warp >> 2;
    const int band    = warp & 3;
    const int NT0     = half2nd * 3;
    const int NTN     = half2nd ? 2 : 3;

    float cacc[3][4];
#pragma unroll
    for (int t = 0; t < 3; t++)
#pragma unroll
        for (int q = 0; q < 4; q++) cacc[t][q] = 0.f;

    for (int kk2 = 0; kk2 < 4; kk2++) {
#pragma unroll
        for (int l = 0; l < 5; l++) {
            int f = tid + l * 256;
            int kp = f / 40;
            int n  = f - kp * 40;
            int krow = kk2 * 64 + 2 * kp;
            __half2 p = __floats2half2_rn(W2[krow * FCLS + n],
                                          W2[(krow + 1) * FCLS + n]);
            Ws32[kp * WSS + n] = *(unsigned*)&p;
        }
        if (wn == kk2) {
#pragma unroll
            for (int mt = 0; mt < 2; mt++) {
                int r0 = wm * 32 + mt * 16 + g;
#pragma unroll
                for (int nt = 0; nt < 8; nt++) {
                    int col = kk2 * 64 + nt * 8 + tk * 2;
                    float bb0 = b1[col], bb1 = b1[col + 1];
                    int cp = nt * 4 + tk;
                    __half2 p0 = __floats2half2_rn(fmaxf(c[mt][nt][0] + bb0, 0.f),
                                                   fmaxf(c[mt][nt][1] + bb1, 0.f));
                    __half2 p1 = __floats2half2_rn(fmaxf(c[mt][nt][2] + bb0, 0.f),
                                                   fmaxf(c[mt][nt][3] + bb1, 0.f));
                    Hs32[r0 * HSS + cp]       = *(unsigned*)&p0;
                    Hs32[(r0 + 8) * HSS + cp] = *(unsigned*)&p1;
                }
            }
        }
        __syncthreads();

#pragma unroll
        for (int s = 0; s < 4; s++) {
            int p  = tk + s * 8;
            int rb = band * 16 + g;
            unsigned a0 = Hs32[rb * HSS + p];
            unsigned a1 = Hs32[(rb + 8) * HSS + p];
            unsigned a2 = Hs32[rb * HSS + p + 4];
            unsigned a3 = Hs32[(rb + 8) * HSS + p + 4];
#pragma unroll
            for (int t = 0; t < 3; t++) {
                if (t < NTN) {
                    int n = (NT0 + t) * 8 + g;
                    unsigned b0  = Ws32[p * WSS + n];
                    unsigned b1v = Ws32[(p + 4) * WSS + n];
                    mma_f16(cacc[t], a0, a1, a2, a3, b0, b1v);
                }
            }
        }
        __syncthreads();
    }

    int r0 = row0 + band * 16 + g;
#pragma unroll
    for (int t = 0; t < 3; t++) {
        if (t < NTN) {
            int col = (NT0 + t) * 8 + tk * 2;
            float bb0 = b2[col], bb1 = b2[col + 1];
            *(float2*)(out + r0 * FCLS + col) =
                make_float2(cacc[t][0] + bb0, cacc[t][1] + bb1);
            *(float2*)(out + (r0 + 8) * FCLS + col) =
                make_float2(cacc[t][2] + bb0, cacc[t][3] + bb1);
        }
    }
}

// ---------------------------------------------------------------
extern "C" void kernel_launch(void* const* d_in, const int* in_sizes, int n_in,
                              void* d_out, int out_size) {
    const float* features = (const float*)d_in[0];
    const int*   src      = (const int*)d_in[1];
    const int*   dst      = (const int*)d_in[2];
    const float* W1       = (const float*)d_in[3];
    const float* b1       = (const float*)d_in[4];
    const float* W2       = (const float*)d_in[5];
    const float* b2       = (const float*)d_in[6];
    float*       out      = (float*)d_out;

    __half *feat_h, *buf1h;
    float *norm, *norm2;
    int *degp;
    cudaGetSymbolAddress((void**)&feat_h, g_feat_h);
    cudaGetSymbolAddress((void**)&buf1h,  g_buf1h);
    cudaGetSymbolAddress((void**)&norm,   g_norm);
    cudaGetSymbolAddress((void**)&norm2,  g_norm2);
    cudaGetSymbolAddress((void**)&degp,   g_deg);

    // CSR build
    cudaMemsetAsync(degp, 0, NN * sizeof(int));
    count_deg_kernel<<<(EE / 4 + 255) / 256, 256>>>(dst);
    scan_phase1<<<NSB, SCAN_BLK>>>();
    scan_phase3<<<NSB, SCAN_BLK>>>();

    // fused: CSR fill + fp16 feature conversion
    fill_conv_kernel<<<FILL_BLKS + CONV_BLKS, 256>>>(src, dst, features);

    // hop1: buf1h = half(norm^2 * A feat_h)
    hop_h_kernel<<<(NN * 32 + 255) / 256, 256>>>(feat_h, buf1h, norm2);

    // fused hop2 + MLP head
    gemm12_fused<<<NN / 64, 256>>>(buf1h, W1, b1, W2, b2, out);
}

// round 16
// speedup vs baseline: 1.2226x; 1.2226x over previous
#include <cuda_runtime.h>
#include <cuda_fp16.h>
#include <cstdint>

#define NN   40000
#define EE   640000
#define FIN  128
#define FHID 256
#define FCLS 40

#define SCAN_BLK 256
#define NSB ((NN + SCAN_BLK - 1) / SCAN_BLK)   // 157

#define FILL_BLKS ((EE / 4 + 255) / 256)         // 625
#define CONV_BLKS ((NN * (FIN / 4) + 255) / 256) // 5000 (float4 per thread)

// ---- scratch (no allocation allowed -> __device__ globals) ----
__device__ int    g_deg[NN];
__device__ int    g_rowptr[NN + 1];
__device__ int    g_cur[NN];
__device__ int    g_colidx[EE];
__device__ int    g_bsum[NSB];
__device__ float  g_norm[NN];
__device__ float  g_norm2[NN];
__device__ __half g_feat_h[NN * FIN];   // norm * X        (fp16)
__device__ __half g_buf1h[NN * FIN];    // N^2 A N X       (fp16)
__device__ __half g_buf2h[NN * FIN];    // N A N^2 A N X   (fp16, GEMM A)

// ---------------------------------------------------------------
__device__ __forceinline__ void mma_f16(float c[4],
                                        unsigned a0, unsigned a1, unsigned a2, unsigned a3,
                                        unsigned b0, unsigned b1) {
    asm volatile(
        "mma.sync.aligned.m16n8k16.row.col.f32.f16.f16.f32 "
        "{%0,%1,%2,%3}, {%4,%5,%6,%7}, {%8,%9}, {%0,%1,%2,%3};"
        : "+f"(c[0]), "+f"(c[1]), "+f"(c[2]), "+f"(c[3])
        : "r"(a0), "r"(a1), "r"(a2), "r"(a3), "r"(b0), "r"(b1));
}

// ---------------------------------------------------------------
// degree histogram (no-return atomics -> REDG), 4 edges/thread
__global__ void count_deg_kernel(const int* __restrict__ dst) {
    int e = blockIdx.x * blockDim.x + threadIdx.x;
    if (e < EE / 4) {
        int4 d = ((const int4*)dst)[e];
        atomicAdd(&g_deg[d.x], 1);
        atomicAdd(&g_deg[d.y], 1);
        atomicAdd(&g_deg[d.z], 1);
        atomicAdd(&g_deg[d.w], 1);
    }
}

// ---- 2-phase scan: block sums, then per-block base computed in-place ----
__global__ void scan_phase1() {
    __shared__ int wsum[8];
    int tid = threadIdx.x, w = tid >> 5, l = tid & 31;
    int i = blockIdx.x * SCAN_BLK + tid;
    int s = (i < NN) ? g_deg[i] : 0;
#pragma unroll
    for (int o = 16; o; o >>= 1) s += __shfl_down_sync(~0u, s, o);
    if (l == 0) wsum[w] = s;
    __syncthreads();
    if (tid == 0) {
        int t = 0;
#pragma unroll
        for (int k = 0; k < 8; k++) t += wsum[k];
        g_bsum[blockIdx.x] = t;
    }
}

__global__ void scan_phase3() {
    __shared__ int ws[8];
    __shared__ int bsr[8];
    const int bid = blockIdx.x;
    int tid = threadIdx.x, w = tid >> 5, l = tid & 31;

    // block base = sum of g_bsum[0..bid)  (NSB=157 <= 256 threads)
    int bv = (tid < bid) ? g_bsum[tid] : 0;
#pragma unroll
    for (int o = 16; o; o >>= 1) bv += __shfl_down_sync(~0u, bv, o);
    if (l == 0) bsr[w] = bv;

    int i = bid * SCAN_BLK + tid;
    int v = (i < NN) ? g_deg[i] : 0;
    int incl = v;
#pragma unroll
    for (int o = 1; o < 32; o <<= 1) {
        int t = __shfl_up_sync(~0u, incl, o);
        if (l >= o) incl += t;
    }
    if (l == 31) ws[w] = incl;
    __syncthreads();
    if (tid < 8) {
        int t = ws[tid];
#pragma unroll
        for (int o = 1; o < 8; o <<= 1) {
            int u = __shfl_up_sync(0xffu, t, o);
            if (tid >= o) t += u;
        }
        ws[tid] = t;
    }
    __syncthreads();
    int base = bsr[0] + bsr[1] + bsr[2] + bsr[3] +
               bsr[4] + bsr[5] + bsr[6] + bsr[7];
    int excl = base + ((w > 0) ? ws[w - 1] : 0) + incl - v;
    if (i < NN) {
        g_rowptr[i] = excl;
        g_cur[i]    = excl;
        float dn = fmaxf((float)v, 1.0f);
        float nv = rsqrtf(dn);
        g_norm[i]  = nv;
        g_norm2[i] = nv * nv;
        if (i == NN - 1) g_rowptr[NN] = excl + v;
    }
}

// ---------------------------------------------------------------
// FUSED: CSR fill (blocks 0..FILL_BLKS-1) + fp16 feature conversion (rest).
__global__ void fill_conv_kernel(const int* __restrict__ src,
                                 const int* __restrict__ dst,
                                 const float* __restrict__ X) {
    int b = blockIdx.x;
    if (b < FILL_BLKS) {
        int e = b * 256 + threadIdx.x;
        if (e < EE / 4) {
            int4 s = ((const int4*)src)[e];
            int4 d = ((const int4*)dst)[e];
            g_colidx[atomicAdd(&g_cur[d.x], 1)] = s.x;
            g_colidx[atomicAdd(&g_cur[d.y], 1)] = s.y;
            g_colidx[atomicAdd(&g_cur[d.z], 1)] = s.z;
            g_colidx[atomicAdd(&g_cur[d.w], 1)] = s.w;
        }
    } else {
        int i = (b - FILL_BLKS) * 256 + threadIdx.x;   // float4 index
        if (i < NN * (FIN / 4)) {
            int row = i >> 5;
            float4 v = ((const float4*)X)[i];
            float nv = __ldg(&g_norm[row]);
            uint2 o;
            *(__half2*)&o.x = __floats2half2_rn(v.x * nv, v.y * nv);
            *(__half2*)&o.y = __floats2half2_rn(v.z * nv, v.w * nv);
            ((uint2*)g_feat_h)[i] = o;
        }
    }
}

// ---------------------------------------------------------------
// propagation hop, fp16 rows, MLP=4 (proven loop): warp per dst node.
__global__ void hop_h_kernel(const __half* __restrict__ hin,
                             __half* __restrict__ hout,
                             const float* __restrict__ oscale) {
    int w    = (blockIdx.x * blockDim.x + threadIdx.x) >> 5;
    int lane = threadIdx.x & 31;
    if (w >= NN) return;

    int j  = g_rowptr[w];
    int je = g_rowptr[w + 1];

    const uint2* hin2 = (const uint2*)hin;
    float4 accA = make_float4(0.f, 0.f, 0.f, 0.f);
    float4 accB = make_float4(0.f, 0.f, 0.f, 0.f);

#define ACC(ACCV, V)                                         \
    {                                                        \
        float2 _p0 = __half22float2(*(__half2*)&(V).x);      \
        float2 _p1 = __half22float2(*(__half2*)&(V).y);      \
        ACCV.x += _p0.x; ACCV.y += _p0.y;                    \
        ACCV.z += _p1.x; ACCV.w += _p1.y;                    \
    }

    for (; j + 4 <= je; j += 4) {
        int s0 = __ldg(&g_colidx[j]);
        int s1 = __ldg(&g_colidx[j + 1]);
        int s2 = __ldg(&g_colidx[j + 2]);
        int s3 = __ldg(&g_colidx[j + 3]);
        uint2 v0 = hin2[s0 * 32 + lane];
        uint2 v1 = hin2[s1 * 32 + lane];
        uint2 v2 = hin2[s2 * 32 + lane];
        uint2 v3 = hin2[s3 * 32 + lane];
        ACC(accA, v0) ACC(accB, v1) ACC(accA, v2) ACC(accB, v3)
    }
    if (j + 2 <= je) {
        int s0 = __ldg(&g_colidx[j]);
        int s1 = __ldg(&g_colidx[j + 1]);
        uint2 v0 = hin2[s0 * 32 + lane];
        uint2 v1 = hin2[s1 * 32 + lane];
        ACC(accA, v0) ACC(accB, v1)
        j += 2;
    }
    if (j < je) {
        int s0 = __ldg(&g_colidx[j]);
        uint2 v0 = hin2[s0 * 32 + lane];
        ACC(accA, v0)
    }
#undef ACC

    float os = oscale[w];
    float4 acc;
    acc.x = (accA.x + accB.x) * os;
    acc.y = (accA.y + accB.y) * os;
    acc.z = (accA.z + accB.z) * os;
    acc.w = (accA.w + accB.w) * os;

    uint2 o;
    *(__half2*)&o.x = __floats2half2_rn(acc.x, acc.y);
    *(__half2*)&o.y = __floats2half2_rn(acc.z, acc.w);
    ((uint2*)hout)[w * 32 + lane] = o;
}

// ---------------------------------------------------------------
// Fused MLP head on fp16 tensor cores (fp32 accumulate), STATIC 22KB smem.
// (R11 proven config: standalone, buf2h as A input)
#define ASH 40    // As stride in halves  (As32 step 20 -> conflict-free)
#define BPS 264   // Bp stride in u32     (step 8  -> conflict-free)
#define HSS 36    // Hs stride in u32     (step 4  -> conflict-free)
#define WSS 40    // Ws stride in u32     (step 8  -> conflict-free)

__global__ __launch_bounds__(256) void gemm12_h(const __half* __restrict__ A,
                                                const float* __restrict__ W1,
                                                const float* __restrict__ b1,
                                                const float* __restrict__ W2,
                                                const float* __restrict__ b2,
                                                float* __restrict__ out) {
    __shared__ __align__(16) unsigned SM[1280 + 16 * BPS];   // 22016 B
    __half*   As16 = (__half*)SM;
    unsigned* Bp32 = SM + 1280;
    unsigned* Hs32 = SM;
    unsigned* Ws32 = SM + 2304;

    const int tid  = threadIdx.x;
    const int lane = tid & 31;
    const int warp = tid >> 5;
    const int wm   = warp >> 2;        // 0..1
    const int wn   = warp & 3;         // 0..3
    const int row0 = blockIdx.x * 64;
    const int g    = lane >> 2;        // 0..7
    const int tk   = lane & 3;         // 0..3

    float c[2][8][4];
#pragma unroll
    for (int i = 0; i < 2; i++)
#pragma unroll
        for (int jj = 0; jj < 8; jj++)
#pragma unroll
            for (int q = 0; q < 4; q++) c[i][jj][q] = 0.f;

    // ---------------- phase 1: H = A @ W1 ----------------
    for (int kk = 0; kk < 4; kk++) {
#pragma unroll
        for (int l = 0; l < 2; l++) {
            int f   = tid + l * 256;
            int r   = f >> 3;
            int c4  = (f & 7) * 4;
            uint2 v = *(const uint2*)(A + (row0 + r) * FIN + kk * 32 + c4);
            *(uint2*)(As16 + r * ASH + c4) = v;
        }
#pragma unroll
        for (int l = 0; l < 4; l++) {
            int f    = tid + l * 256;
            int kp   = f >> 6;
            int n4   = (f & 63) * 4;
            int krow = kk * 32 + 2 * kp;
            float4 w0 = *(const float4*)(W1 + krow * FHID + n4);
            float4 w1 = *(const float4*)(W1 + (krow + 1) * FHID + n4);
            uint4 pk;
            { __half2 p = __floats2half2_rn(w0.x, w1.x); pk.x = *(unsigned*)&p; }
            { __half2 p = __floats2half2_rn(w0.y, w1.y); pk.y = *(unsigned*)&p; }
            { __half2 p = __floats2half2_rn(w0.z, w1.z); pk.z = *(unsigned*)&p; }
            { __half2 p = __floats2half2_rn(w0.w, w1.w); pk.w = *(unsigned*)&p; }
            *(uint4*)(Bp32 + kp * BPS + n4) = pk;
        }
        __syncthreads();

        const unsigned* As32 = (const unsigned*)As16;
#pragma unroll
        for (int s = 0; s < 2; s++) {
            int p = tk + s * 8;
            unsigned a[2][4];
#pragma unroll
            for (int mt = 0; mt < 2; mt++) {
                int rb = wm * 32 + mt * 16 + g;
                a[mt][0] = As32[rb * (ASH / 2) + p];
                a[mt][1] = As32[(rb + 8) * (ASH / 2) + p];
                a[mt][2] = As32[rb * (ASH / 2) + p + 4];
                a[mt][3] = As32[(rb + 8) * (ASH / 2) + p + 4];
            }
#pragma unroll
            for (int nt = 0; nt < 8; nt++) {
                int n = wn * 64 + nt * 8 + g;
                unsigned b0  = Bp32[p * BPS + n];
                unsigned b1v = Bp32[(p + 4) * BPS + n];
#pragma unroll
                for (int mt = 0; mt < 2; mt++)
                    mma_f16(c[mt][nt], a[mt][0], a[mt][1], a[mt][2], a[mt][3],
                            b0, b1v);
            }
        }
        __syncthreads();
    }

    // ---------------- phase 2: out = relu(H + b1) @ W2 + b2 ----------------
    const int half2nd = warp >> 2;
    const int band    = warp & 3;
    const int NT0     = half2nd * 3;
    const int NTN     = half2nd ? 2 : 3;

    float cacc[3][4];
#pragma unroll
    for (int t = 0; t < 3; t++)
#pragma unroll
        for (int q = 0; q < 4; q++) cacc[t][q] = 0.f;

    for (int kk2 = 0; kk2 < 4; kk2++) {
#pragma unroll
        for (int l = 0; l < 5; l++) {
            int f = tid + l * 256;
            int kp = f / 40;
            int n  = f - kp * 40;
            int krow = kk2 * 64 + 2 * kp;
            __half2 p = __floats2half2_rn(W2[krow * FCLS + n],
                                          W2[(krow + 1) * FCLS + n]);
            Ws32[kp * WSS + n] = *(unsigned*)&p;
        }
        if (wn == kk2) {
#pragma unroll
            for (int mt = 0; mt < 2; mt++) {
                int r0 = wm * 32 + mt * 16 + g;
#pragma unroll
                for (int nt = 0; nt < 8; nt++) {
                    int col = kk2 * 64 + nt * 8 + tk * 2;
                    float bb0 = b1[col], bb1 = b1[col + 1];
                    int cp = nt * 4 + tk;
                    __half2 p0 = __floats2half2_rn(fmaxf(c[mt][nt][0] + bb0, 0.f),
                                                   fmaxf(c[mt][nt][1] + bb1, 0.f));
                    __half2 p1 = __floats2half2_rn(fmaxf(c[mt][nt][2] + bb0, 0.f),
                                                   fmaxf(c[mt][nt][3] + bb1, 0.f));
                    Hs32[r0 * HSS + cp]       = *(unsigned*)&p0;
                    Hs32[(r0 + 8) * HSS + cp] = *(unsigned*)&p1;
                }
            }
        }
        __syncthreads();

#pragma unroll
        for (int s = 0; s < 4; s++) {
            int p  = tk + s * 8;
            int rb = band * 16 + g;
            unsigned a0 = Hs32[rb * HSS + p];
            unsigned a1 = Hs32[(rb + 8) * HSS + p];
            unsigned a2 = Hs32[rb * HSS + p + 4];
            unsigned a3 = Hs32[(rb + 8) * HSS + p + 4];
#pragma unroll
            for (int t = 0; t < 3; t++) {
                if (t < NTN) {
                    int n = (NT0 + t) * 8 + g;
                    unsigned b0  = Ws32[p * WSS + n];
                    unsigned b1v = Ws32[(p + 4) * WSS + n];
                    mma_f16(cacc[t], a0, a1, a2, a3, b0, b1v);
                }
            }
        }
        __syncthreads();
    }

    int r0 = row0 + band * 16 + g;
#pragma unroll
    for (int t = 0; t < 3; t++) {
        if (t < NTN) {
            int col = (NT0 + t) * 8 + tk * 2;
            float bb0 = b2[col], bb1 = b2[col + 1];
            *(float2*)(out + r0 * FCLS + col) =
                make_float2(cacc[t][0] + bb0, cacc[t][1] + bb1);
            *(float2*)(out + (r0 + 8) * FCLS + col) =
                make_float2(cacc[t][2] + bb0, cacc[t][3] + bb1);
        }
    }
}

// ---------------------------------------------------------------
extern "C" void kernel_launch(void* const* d_in, const int* in_sizes, int n_in,
                              void* d_out, int out_size) {
    const float* features = (const float*)d_in[0];
    const int*   src      = (const int*)d_in[1];
    const int*   dst      = (const int*)d_in[2];
    const float* W1       = (const float*)d_in[3];
    const float* b1       = (const float*)d_in[4];
    const float* W2       = (const float*)d_in[5];
    const float* b2       = (const float*)d_in[6];
    float*       out      = (float*)d_out;

    __half *feat_h, *buf1h, *buf2h;
    float *norm, *norm2;
    int *degp;
    cudaGetSymbolAddress((void**)&feat_h, g_feat_h);
    cudaGetSymbolAddress((void**)&buf1h,  g_buf1h);
    cudaGetSymbolAddress((void**)&buf2h,  g_buf2h);
    cudaGetSymbolAddress((void**)&norm,   g_norm);
    cudaGetSymbolAddress((void**)&norm2,  g_norm2);
    cudaGetSymbolAddress((void**)&degp,   g_deg);

    // CSR build (merged scan: one launch fewer than R11)
    cudaMemsetAsync(degp, 0, NN * sizeof(int));
    count_deg_kernel<<<(EE / 4 + 255) / 256, 256>>>(dst);
    scan_phase1<<<NSB, SCAN_BLK>>>();
    scan_phase3<<<NSB, SCAN_BLK>>>();

    // fused: CSR fill + fp16 feature conversion
    fill_conv_kernel<<<FILL_BLKS + CONV_BLKS, 256>>>(src, dst, features);

    // hop1: buf1h = half(norm^2 * A feat_h);  hop2: buf2h = half(norm * A buf1h)
    hop_h_kernel<<<(NN * 32 + 255) / 256, 256>>>(feat_h, buf1h, norm2);
    hop_h_kernel<<<(NN * 32 + 255) / 256, 256>>>(buf1h, buf2h, norm);

    // standalone fused MLP head (R11 proven, 22KB static smem)
    gemm12_h<<<NN / 64, 256>>>(buf2h, W1, b1, W2, b2, out);
}